// round 1
// baseline (speedup 1.0000x reference)
#include <cuda_runtime.h>
#include <math.h>

// Problem constants (shapes are fixed by the dataset).
#define D 256              // d_in == d_out == 256
#define N_TGT_MAX 40000

// Scratch for the SpMM result (mapped): 40000 x 256 fp32 = 40.96 MB.
// __device__ global array is the sanctioned no-alloc scratch mechanism.
__device__ float g_mapped[N_TGT_MAX * D];

// ---------------------------------------------------------------------------
// Kernel 0: zero the mapped scratch (float4 stores).
// ---------------------------------------------------------------------------
__global__ void zero_mapped_kernel(int n_float4) {
    int idx = blockIdx.x * blockDim.x + threadIdx.x;
    if (idx < n_float4) {
        ((float4*)g_mapped)[idx] = make_float4(0.f, 0.f, 0.f, 0.f);
    }
}

// ---------------------------------------------------------------------------
// Kernel 1: SpMM scatter.  One warp per edge; each lane handles 2 float4
// (8 floats) of the 256-wide row.  mapped[r,:] += vals[e] * x[c,:].
// ---------------------------------------------------------------------------
__global__ void spmm_scatter_kernel(const float* __restrict__ x,
                                    const int* __restrict__ rows,
                                    const int* __restrict__ cols,
                                    const float* __restrict__ vals,
                                    int nnz) {
    int e = blockIdx.x * 8 + (threadIdx.x >> 5);
    if (e >= nnz) return;
    int lane = threadIdx.x & 31;

    int r = rows[e];
    int c = cols[e];
    float v = vals[e];

    const float4* xs = (const float4*)(x + (size_t)c * D);
    float* mr = g_mapped + (size_t)r * D;

#pragma unroll
    for (int j = 0; j < 2; ++j) {
        int q = lane + j * 32;          // float4 index 0..63
        float4 xv = xs[q];
        int base = q * 4;
        atomicAdd(mr + base + 0, v * xv.x);
        atomicAdd(mr + base + 1, v * xv.y);
        atomicAdd(mr + base + 2, v * xv.z);
        atomicAdd(mr + base + 3, v * xv.w);
    }
}

// ---------------------------------------------------------------------------
// Kernel 2: fused GEMM (mapped @ W + b) + LayerNorm + exact GELU.
// Block: 256 threads, computes a BM=32 x 256 output tile, K = 256.
// Thread (tx = tid%64, ty = tid/64) owns an 8x4 register tile:
//   rows ty*8 .. ty*8+7, cols tx*4 .. tx*4+3.
// Per k: 1 LDS.128 (W) + 8 broadcast LDS (M) feeding 32 FFMA -> FMA-bound.
// ---------------------------------------------------------------------------
__global__ __launch_bounds__(256) void gemm_ln_gelu_kernel(
        const float* __restrict__ W,       // [256,256] row-major (k, c)
        const float* __restrict__ bias,    // [256]
        const float* __restrict__ gamma,   // [256]
        const float* __restrict__ beta,    // [256]
        float* __restrict__ out) {
    __shared__ __align__(16) float sW[32 * 256];   // W k-tile: [kk][c]
    __shared__ __align__(16) float sM[32 * 36];    // mapped tile: [r][kk], pad 4

    const int tid = threadIdx.x;
    const int tx = tid & 63;
    const int ty = tid >> 6;
    const int row0 = blockIdx.x * 32;

    float acc[8][4];
#pragma unroll
    for (int i = 0; i < 8; ++i)
#pragma unroll
        for (int j = 0; j < 4; ++j) acc[i][j] = 0.f;

#pragma unroll 1
    for (int kt = 0; kt < 8; ++kt) {
        const int k0 = kt * 32;
        // --- load W tile: rows k0..k0+31, all 256 cols (8192 floats) ---
        {
            const float4* Wv = (const float4*)(W + (size_t)k0 * D);
            float4* sWv = (float4*)sW;
#pragma unroll
            for (int i = 0; i < 8; ++i)
                sWv[tid + i * 256] = Wv[tid + i * 256];
        }
        // --- load mapped tile: 32 rows x 32 k (1024 floats = 256 float4) ---
        {
            int r = tid >> 3;
            int kk = (tid & 7) * 4;
            float4 mv = *(const float4*)(g_mapped + (size_t)(row0 + r) * D + k0 + kk);
            *(float4*)&sM[r * 36 + kk] = mv;
        }
        __syncthreads();

#pragma unroll
        for (int kk = 0; kk < 32; ++kk) {
            float4 wv = *(const float4*)&sW[kk * 256 + tx * 4];
#pragma unroll
            for (int i = 0; i < 8; ++i) {
                float mv = sM[(ty * 8 + i) * 36 + kk];
                acc[i][0] += mv * wv.x;
                acc[i][1] += mv * wv.y;
                acc[i][2] += mv * wv.z;
                acc[i][3] += mv * wv.w;
            }
        }
        __syncthreads();
    }

    // --- bias add, stage h tile into shared (reuse sW region) ---
    float* sH = sW;   // sW no longer needed
    {
        float4 bv = *(const float4*)(bias + tx * 4);
#pragma unroll
        for (int i = 0; i < 8; ++i) {
            float4 h4 = make_float4(acc[i][0] + bv.x, acc[i][1] + bv.y,
                                    acc[i][2] + bv.z, acc[i][3] + bv.w);
            *(float4*)&sH[(ty * 8 + i) * 256 + tx * 4] = h4;
        }
    }
    __syncthreads();

    // --- LayerNorm + GELU: warp w handles rows w*4 .. w*4+3 ---
    const int warp = tid >> 5;
    const int lane = tid & 31;
#pragma unroll
    for (int rr = 0; rr < 4; ++rr) {
        const int r = warp * 4 + rr;
        float v[8];
        float s = 0.f;
#pragma unroll
        for (int j = 0; j < 8; ++j) {
            v[j] = sH[r * 256 + lane + j * 32];
            s += v[j];
        }
#pragma unroll
        for (int o = 16; o; o >>= 1) s += __shfl_xor_sync(0xffffffffu, s, o);
        const float mu = s * (1.f / 256.f);

        float q = 0.f;
#pragma unroll
        for (int j = 0; j < 8; ++j) {
            float d = v[j] - mu;
            q += d * d;
        }
#pragma unroll
        for (int o = 16; o; o >>= 1) q += __shfl_xor_sync(0xffffffffu, q, o);
        const float rstd = rsqrtf(q * (1.f / 256.f) + 1e-5f);

        float* orow = out + (size_t)(row0 + r) * D;
#pragma unroll
        for (int j = 0; j < 8; ++j) {
            const int c = lane + j * 32;
            float t = (v[j] - mu) * rstd * gamma[c] + beta[c];
            // exact GELU: 0.5 * t * (1 + erf(t / sqrt(2)))
            orow[c] = 0.5f * t * (1.f + erff(t * 0.70710678118654752f));
        }
    }
}

// ---------------------------------------------------------------------------
// Launch.  Inputs (metadata order): x, rows, cols, vals, W, b, gamma, beta,
// num_targets.
// ---------------------------------------------------------------------------
extern "C" void kernel_launch(void* const* d_in, const int* in_sizes, int n_in,
                              void* d_out, int out_size) {
    const float* x     = (const float*)d_in[0];
    const int*   rows  = (const int*)d_in[1];
    const int*   cols  = (const int*)d_in[2];
    const float* vals  = (const float*)d_in[3];
    const float* W     = (const float*)d_in[4];
    const float* bias  = (const float*)d_in[5];
    const float* gamma = (const float*)d_in[6];
    const float* beta  = (const float*)d_in[7];

    const int nnz   = in_sizes[1];
    const int n_tgt = out_size / D;       // 40000

    // 1) zero the SpMM accumulator scratch
    {
        int n_f4 = n_tgt * D / 4;
        int threads = 256;
        int blocks = (n_f4 + threads - 1) / threads;
        zero_mapped_kernel<<<blocks, threads>>>(n_f4);
    }
    // 2) SpMM scatter (one warp per edge, 8 edges per 256-thread block)
    {
        int blocks = (nnz + 7) / 8;
        spmm_scatter_kernel<<<blocks, 256>>>(x, rows, cols, vals, nnz);
    }
    // 3) fused GEMM + bias + LayerNorm + GELU (BM=32 rows per block)
    {
        int blocks = n_tgt / 32;          // 40000 / 32 = 1250, exact
        gemm_ln_gelu_kernel<<<blocks, 256>>>(W, bias, gamma, beta, (float*)d_out);
    }
}

// round 3
// speedup vs baseline: 2.0841x; 2.0841x over previous
#include <cuda_runtime.h>
#include <cuda_bf16.h>
#include <math.h>
#include <stdint.h>

#define D 256
#define N_TGT 40000
#define BM 64
#define NBLK (N_TGT / BM)            // 625, exact
#define KC 32                        // k-chunk
#define NCHUNK (D / KC)              // 8

// SpMM scratch: 40000 x 256 fp32 = 40.96 MB
__device__ float g_mapped[(size_t)N_TGT * D];
// Pre-transposed, bf16-split weights: Wt[n][k] = W[k][n]
__device__ __nv_bfloat16 g_wt_hi[D * D];
__device__ __nv_bfloat16 g_wt_lo[D * D];

// ---------------------------------------------------------------------------
// SMEM layout (bytes).  Staging region is reused for the h tile in phase 2.
//   A tiles: 64 rows x 40 bf16 (80 B rows, pad kills LDS frag conflicts)
//   B tiles: 256 rows x 40 bf16
// ---------------------------------------------------------------------------
#define SOFF_AHI 0
#define SOFF_ALO 5120
#define SOFF_BHI 10240
#define SOFF_BLO 30720
// h tile (phase 2): 64 rows x 260 floats = 66560 B (overlaps staging)
#define SOFF_H 0
#define H_STRIDE 260
#define SOFF_BIAS 66560
#define SOFF_GAMMA 67584
#define SOFF_BETA 68608
#define SMEM_TOTAL 69632

__device__ __forceinline__ void split2(float f0, float f1,
                                       uint32_t& hi, uint32_t& lo) {
    __nv_bfloat16 h0 = __float2bfloat16(f0);
    __nv_bfloat16 h1 = __float2bfloat16(f1);
    __nv_bfloat16 l0 = __float2bfloat16(f0 - __bfloat162float(h0));
    __nv_bfloat16 l1 = __float2bfloat16(f1 - __bfloat162float(h1));
    __nv_bfloat162 hp(h0, h1), lp(l0, l1);
    hi = *(uint32_t*)&hp;
    lo = *(uint32_t*)&lp;
}

__device__ __forceinline__ void mma_bf16(float* c, const uint32_t* a,
                                         uint32_t b0, uint32_t b1) {
    asm volatile(
        "mma.sync.aligned.m16n8k16.row.col.f32.bf16.bf16.f32 "
        "{%0,%1,%2,%3}, {%4,%5,%6,%7}, {%8,%9}, {%0,%1,%2,%3};"
        : "+f"(c[0]), "+f"(c[1]), "+f"(c[2]), "+f"(c[3])
        : "r"(a[0]), "r"(a[1]), "r"(a[2]), "r"(a[3]), "r"(b0), "r"(b1));
}

// ---------------------------------------------------------------------------
// Kernel 0: transpose + bf16-split W.  16 blocks x 256 threads.
// ---------------------------------------------------------------------------
__global__ __launch_bounds__(256) void wconv_kernel(const float* __restrict__ W) {
    __shared__ float tile[16][257];
    const int tid = threadIdx.x;
    const int k0 = blockIdx.x * 16;
#pragma unroll
    for (int i = 0; i < 16; ++i) {
        int idx = i * 256 + tid;
        int kr = idx >> 8, n = idx & 255;
        tile[kr][n] = W[(size_t)(k0 + kr) * D + n];
    }
    __syncthreads();
#pragma unroll
    for (int i = 0; i < 16; ++i) {
        int task = i * 256 + tid;
        int n = task >> 4, kr = task & 15;
        float v = tile[kr][n];
        __nv_bfloat16 h = __float2bfloat16(v);
        __nv_bfloat16 l = __float2bfloat16(v - __bfloat162float(h));
        g_wt_hi[(size_t)n * D + k0 + kr] = h;
        g_wt_lo[(size_t)n * D + k0 + kr] = l;
    }
}

// ---------------------------------------------------------------------------
// Kernel 1: SpMM scatter, one warp per edge, red.global.add.v4.f32.
// ---------------------------------------------------------------------------
__global__ void spmm_scatter_kernel(const float* __restrict__ x,
                                    const int* __restrict__ rows,
                                    const int* __restrict__ cols,
                                    const float* __restrict__ vals,
                                    int nnz) {
    int e = blockIdx.x * 8 + (threadIdx.x >> 5);
    if (e >= nnz) return;
    int lane = threadIdx.x & 31;

    int r = __ldg(rows + e);
    int c = __ldg(cols + e);
    float v = __ldg(vals + e);

    const float4* xs = (const float4*)(x + (size_t)c * D);
    float4* mr = (float4*)(g_mapped + (size_t)r * D);

    float4 x0 = __ldg(xs + lane);
    float4 x1 = __ldg(xs + lane + 32);
    asm volatile("red.global.add.v4.f32 [%0], {%1, %2, %3, %4};"
                 :: "l"(mr + lane), "f"(v * x0.x), "f"(v * x0.y),
                    "f"(v * x0.z), "f"(v * x0.w) : "memory");
    asm volatile("red.global.add.v4.f32 [%0], {%1, %2, %3, %4};"
                 :: "l"(mr + lane + 32), "f"(v * x1.x), "f"(v * x1.y),
                    "f"(v * x1.z), "f"(v * x1.w) : "memory");
}

// ---------------------------------------------------------------------------
// Kernel 2: bf16-split tensor-core GEMM (mapped @ W + b) + LayerNorm + GELU.
// 256 threads, BM=64 x 256 tile.  Warp grid: warp_m = wid&1 (32 rows),
// warp_n = wid>>1 (64 cols).  3-MMA compensated bf16: AhiBhi+AhiBlo+AloBhi.
// ---------------------------------------------------------------------------
extern __shared__ char dynsmem[];

__global__ __launch_bounds__(256, 2) void gemm_ln_gelu_kernel(
        const float* __restrict__ bias,
        const float* __restrict__ gamma,
        const float* __restrict__ beta,
        float* __restrict__ out) {
    char* sm = dynsmem;
    const int tid = threadIdx.x;
    const int wid = tid >> 5;
    const int lane = tid & 31;
    const int gr = lane >> 2;       // group row (0..7)
    const int tc = lane & 3;        // thread-in-group (0..3)
    const int warp_m = wid & 1;
    const int warp_n = wid >> 1;
    const int row0 = blockIdx.x * BM;

    // preload params
    {
        float* sB = (float*)(sm + SOFF_BIAS);
        float* sG = (float*)(sm + SOFF_GAMMA);
        float* sBe = (float*)(sm + SOFF_BETA);
        sB[tid] = bias[tid];
        sG[tid] = gamma[tid];
        sBe[tid] = beta[tid];
    }

    float acc[2][8][4];
#pragma unroll
    for (int mt = 0; mt < 2; ++mt)
#pragma unroll
        for (int nt = 0; nt < 8; ++nt)
#pragma unroll
            for (int q = 0; q < 4; ++q) acc[mt][nt][q] = 0.f;

    const uint16_t* pAhi = (const uint16_t*)(sm + SOFF_AHI);
    const uint16_t* pAlo = (const uint16_t*)(sm + SOFF_ALO);
    const uint16_t* pBhi = (const uint16_t*)(sm + SOFF_BHI);
    const uint16_t* pBlo = (const uint16_t*)(sm + SOFF_BLO);

#pragma unroll 1
    for (int kc = 0; kc < NCHUNK; ++kc) {
        __syncthreads();
        // --- stage A: 64 rows x 32 k fp32 -> bf16 hi/lo ---
        {
            int r = tid >> 2, seg = tid & 3;
            const float4* ap = (const float4*)(g_mapped +
                                (size_t)(row0 + r) * D + kc * KC + seg * 8);
            float4 a0 = __ldg(ap), a1 = __ldg(ap + 1);
            uint32_t h[4], l[4];
            split2(a0.x, a0.y, h[0], l[0]);
            split2(a0.z, a0.w, h[1], l[1]);
            split2(a1.x, a1.y, h[2], l[2]);
            split2(a1.z, a1.w, h[3], l[3]);
            uint32_t off = (uint32_t)(r * 80 + seg * 16);
            *(uint4*)(sm + SOFF_AHI + off) = make_uint4(h[0], h[1], h[2], h[3]);
            *(uint4*)(sm + SOFF_ALO + off) = make_uint4(l[0], l[1], l[2], l[3]);
        }
        // --- stage B: 256 n-rows x 32 k bf16 copy from Wt ---
#pragma unroll
        for (int i = 0; i < 4; ++i) {
            int task = i * 256 + tid;
            int n = task >> 2, seg = task & 3;
            size_t gsrc = (size_t)n * D + kc * KC + seg * 8;   // bf16 idx
            uint32_t off = (uint32_t)(n * 80 + seg * 16);
            *(uint4*)(sm + SOFF_BHI + off) = *(const uint4*)(g_wt_hi + gsrc);
            *(uint4*)(sm + SOFF_BLO + off) = *(const uint4*)(g_wt_lo + gsrc);
        }
        __syncthreads();

        // --- 2 k-steps of mma per chunk ---
#pragma unroll
        for (int ks = 0; ks < 2; ++ks) {
            uint32_t ahi[2][4], alo[2][4];
#pragma unroll
            for (int mt = 0; mt < 2; ++mt) {
                int ar = warp_m * 32 + mt * 16 + gr;
                int ak = ks * 16 + tc * 2;
                const uint16_t* ph = pAhi + ar * 40 + ak;
                const uint16_t* pl = pAlo + ar * 40 + ak;
                ahi[mt][0] = *(const uint32_t*)(ph);
                ahi[mt][1] = *(const uint32_t*)(ph + 320);      // +8 rows
                ahi[mt][2] = *(const uint32_t*)(ph + 8);        // +8 k
                ahi[mt][3] = *(const uint32_t*)(ph + 328);
                alo[mt][0] = *(const uint32_t*)(pl);
                alo[mt][1] = *(const uint32_t*)(pl + 320);
                alo[mt][2] = *(const uint32_t*)(pl + 8);
                alo[mt][3] = *(const uint32_t*)(pl + 328);
            }
#pragma unroll
            for (int nt = 0; nt < 8; ++nt) {
                int bn = warp_n * 64 + nt * 8 + gr;
                int bk = ks * 16 + tc * 2;
                uint32_t bh0 = *(const uint32_t*)(pBhi + bn * 40 + bk);
                uint32_t bh1 = *(const uint32_t*)(pBhi + bn * 40 + bk + 8);
                uint32_t bl0 = *(const uint32_t*)(pBlo + bn * 40 + bk);
                uint32_t bl1 = *(const uint32_t*)(pBlo + bn * 40 + bk + 8);
#pragma unroll
                for (int mt = 0; mt < 2; ++mt) {
                    mma_bf16(acc[mt][nt], ahi[mt], bh0, bh1);
                    mma_bf16(acc[mt][nt], ahi[mt], bl0, bl1);
                    mma_bf16(acc[mt][nt], alo[mt], bh0, bh1);
                }
            }
        }
    }
    __syncthreads();

    // --- stage h = acc + bias into smem ---
    {
        float* sH = (float*)(sm + SOFF_H);
        const float* sB = (const float*)(sm + SOFF_BIAS);
#pragma unroll
        for (int mt = 0; mt < 2; ++mt) {
#pragma unroll
            for (int nt = 0; nt < 8; ++nt) {
                int r = warp_m * 32 + mt * 16 + gr;
                int c = warp_n * 64 + nt * 8 + tc * 2;
                float b0 = sB[c], b1 = sB[c + 1];
                float* p0 = &sH[r * H_STRIDE + c];
                p0[0] = acc[mt][nt][0] + b0;
                p0[1] = acc[mt][nt][1] + b1;
                float* p1 = &sH[(r + 8) * H_STRIDE + c];
                p1[0] = acc[mt][nt][2] + b0;
                p1[1] = acc[mt][nt][3] + b1;
            }
        }
    }
    __syncthreads();

    // --- LayerNorm + exact GELU: warp w handles rows w*8 .. w*8+7 ---
    {
        const float* sH = (const float*)(sm + SOFF_H);
        const float* sG = (const float*)(sm + SOFF_GAMMA);
        const float* sBe = (const float*)(sm + SOFF_BETA);
#pragma unroll
        for (int rr = 0; rr < 8; ++rr) {
            const int r = wid * 8 + rr;
            float v[8];
            float s = 0.f;
#pragma unroll
            for (int j = 0; j < 8; ++j) {
                v[j] = sH[r * H_STRIDE + lane + j * 32];
                s += v[j];
            }
#pragma unroll
            for (int o = 16; o; o >>= 1) s += __shfl_xor_sync(0xffffffffu, s, o);
            const float mu = s * (1.f / 256.f);
            float q = 0.f;
#pragma unroll
            for (int j = 0; j < 8; ++j) {
                float d = v[j] - mu;
                q += d * d;
            }
#pragma unroll
            for (int o = 16; o; o >>= 1) q += __shfl_xor_sync(0xffffffffu, q, o);
            const float rstd = rsqrtf(q * (1.f / 256.f) + 1e-5f);

            float* orow = out + (size_t)(row0 + r) * D;
#pragma unroll
            for (int j = 0; j < 8; ++j) {
                const int c = lane + j * 32;
                float t = (v[j] - mu) * rstd * sG[c] + sBe[c];
                orow[c] = 0.5f * t * (1.f + erff(t * 0.70710678118654752f));
            }
        }
    }
}

// ---------------------------------------------------------------------------
// Launch.  Inputs: x, rows, cols, vals, W, b, gamma, beta, num_targets.
// ---------------------------------------------------------------------------
extern "C" void kernel_launch(void* const* d_in, const int* in_sizes, int n_in,
                              void* d_out, int out_size) {
    const float* x     = (const float*)d_in[0];
    const int*   rows  = (const int*)d_in[1];
    const int*   cols  = (const int*)d_in[2];
    const float* vals  = (const float*)d_in[3];
    const float* W     = (const float*)d_in[4];
    const float* bias  = (const float*)d_in[5];
    const float* gamma = (const float*)d_in[6];
    const float* beta  = (const float*)d_in[7];

    const int nnz = in_sizes[1];

    // 0) zero the SpMM accumulator (memset node is graph-capturable)
    void* mapped_ptr = nullptr;
    cudaGetSymbolAddress(&mapped_ptr, g_mapped);
    cudaMemsetAsync(mapped_ptr, 0, (size_t)N_TGT * D * sizeof(float));

    // 0b) transpose + bf16-split W
    wconv_kernel<<<16, 256>>>(W);

    // 1) SpMM scatter
    spmm_scatter_kernel<<<(nnz + 7) / 8, 256>>>(x, rows, cols, vals, nnz);

    // 2) tensor-core GEMM + bias + LN + GELU
    cudaFuncSetAttribute(gemm_ln_gelu_kernel,
                         cudaFuncAttributeMaxDynamicSharedMemorySize,
                         SMEM_TOTAL);
    gemm_ln_gelu_kernel<<<NBLK, 256, SMEM_TOTAL>>>(
        bias, gamma, beta, (float*)d_out);
}